// round 2
// baseline (speedup 1.0000x reference)
#include <cuda_runtime.h>
#include <math.h>

#define BB 128
#define TT 512
#define HH 1024
#define EE 128
#define NL 17
#define G3 3072        // 3*HH
#define NCTA 128       // persistent CTAs (<=148 SMs, 1 CTA/SM -> co-resident)
#define KC 64          // K-block for recurrent GEMM

// ---------------- device scratch (no cudaMalloc allowed) ----------------
__device__ float g_gxw[201326592];       // [B][T][3H] = 805 MB precomputed w-part of gx
__device__ float g_tbl[NL * G3];          // label_emb @ W_ih[:, :E]^T + b_ih
__device__ float g_hbuf[2][BB * HH];      // double-buffered hidden state
__device__ int   g_prev[BB];              // previous predicted label
__device__ unsigned g_bar_count;
__device__ volatile unsigned g_bar_sense;

// ---------------- helpers ----------------
__device__ __forceinline__ float sigmoidf_(float x) { return 1.0f / (1.0f + expf(-x)); }

// IOBES transition mask. Labels: 0="O", 1+4*type+p with p: B=0,I=1,E=2,S=3.
__device__ __forceinline__ float maskval(int prev, int nxt) {
    bool allowed;
    bool prev_open = (prev == 0) || (((prev - 1) & 3) >= 2);   // O, E-, S-
    if (prev_open) {
        // next must start with O, B, or S
        allowed = (nxt == 0) || (((nxt - 1) & 3) == 0) || (((nxt - 1) & 3) == 3);
    } else {
        // prev is B-t or I-t: next must be I-t or E-t (same type)
        int ty = (prev - 1) >> 2;
        allowed = (nxt != 0) && (((nxt - 1) >> 2) == ty) &&
                  ((((nxt - 1) & 3) == 1) || (((nxt - 1) & 3) == 2));
    }
    return allowed ? 0.0f : -1e12f;
}

// Grid-wide sense-reversing barrier. __threadfence (gpu scope) flushes stores
// to L2 and invalidates L1D (CCTL.IVALL), so plain loads after it are coherent.
__device__ __forceinline__ void gridbar(unsigned& sense) {
    __threadfence();
    __syncthreads();
    if (threadIdx.x == 0) {
        unsigned target = sense ^ 1u;
        if (atomicAdd(&g_bar_count, 1u) == NCTA - 1) {
            atomicExch(&g_bar_count, 0u);
            __threadfence();
            g_bar_sense = target;
        } else {
            while (g_bar_sense != target) { }
        }
        sense = target;
    }
    __syncthreads();
    __threadfence();
}

// ---------------- K1: label-embedding gate table ----------------
__global__ void build_table(const float* __restrict__ label_emb,
                            const float* __restrict__ W_ih,
                            const float* __restrict__ b_ih) {
    int j = blockIdx.x * blockDim.x + threadIdx.x;   // gate column 0..3071
    int l = blockIdx.y;                              // label 0..16
    if (j >= G3) return;
    const float* w = W_ih + (size_t)j * (EE + HH);
    const float* e = label_emb + l * EE;
    float s = b_ih[j];
#pragma unroll 8
    for (int k = 0; k < EE; k++) s += e[k] * w[k];
    g_tbl[l * G3 + j] = s;
}

// ---------------- K2: big SGEMM  g_gxw[m][n] = sum_k we[m][k] * W_ih[n][E+k]
#define BM 128
#define BN 128
#define BK 8
__global__ __launch_bounds__(256) void gxw_gemm(const float* __restrict__ A,
                                                const float* __restrict__ Wih) {
    __shared__ float As[BK][BM + 4];
    __shared__ float Bs[BK][BN + 4];
    const int tid = threadIdx.x;
    const int m0 = blockIdx.y * BM;
    const int n0 = blockIdx.x * BN;
    const int lr = tid >> 1;           // 0..127
    const int lk = (tid & 1) * 4;      // 0 or 4
    const float* pA = A + (size_t)(m0 + lr) * HH + lk;
    const float* pB = Wih + (size_t)(n0 + lr) * (EE + HH) + EE + lk;

    float acc[8][8];
#pragma unroll
    for (int i = 0; i < 8; i++)
#pragma unroll
        for (int j = 0; j < 8; j++) acc[i][j] = 0.0f;

    const int tx = (tid & 15) * 8;
    const int ty = (tid >> 4) * 8;

    float4 fa = *(const float4*)pA;
    float4 fb = *(const float4*)pB;

    for (int k0 = 0; k0 < HH; k0 += BK) {
        As[lk + 0][lr] = fa.x; As[lk + 1][lr] = fa.y;
        As[lk + 2][lr] = fa.z; As[lk + 3][lr] = fa.w;
        Bs[lk + 0][lr] = fb.x; Bs[lk + 1][lr] = fb.y;
        Bs[lk + 2][lr] = fb.z; Bs[lk + 3][lr] = fb.w;
        __syncthreads();
        if (k0 + BK < HH) {
            fa = *(const float4*)(pA + k0 + BK);
            fb = *(const float4*)(pB + k0 + BK);
        }
#pragma unroll
        for (int kk = 0; kk < BK; kk++) {
            float ar[8], br[8];
            *(float4*)&ar[0] = *(float4*)&As[kk][ty];
            *(float4*)&ar[4] = *(float4*)&As[kk][ty + 4];
            *(float4*)&br[0] = *(float4*)&Bs[kk][tx];
            *(float4*)&br[4] = *(float4*)&Bs[kk][tx + 4];
#pragma unroll
            for (int i = 0; i < 8; i++)
#pragma unroll
                for (int j = 0; j < 8; j++) acc[i][j] += ar[i] * br[j];
        }
        __syncthreads();
    }
#pragma unroll
    for (int i = 0; i < 8; i++) {
        size_t row = (size_t)(m0 + ty + i) * G3 + n0 + tx;
        *(float4*)&g_gxw[row]     = make_float4(acc[i][0], acc[i][1], acc[i][2], acc[i][3]);
        *(float4*)&g_gxw[row + 4] = make_float4(acc[i][4], acc[i][5], acc[i][6], acc[i][7]);
    }
}

// ---------------- K3: persistent recurrent kernel ----------------
// 128 CTAs x 256 threads. CTA c owns h-columns [c*8, c*8+8) i.e. gate cols
// {j, 1024+j, 2048+j}. Thread (g = tid>>5, mi = tid&31) computes 4 batch rows
// (mi, mi+32, mi+64, mi+96) x 1 h-column (base+g), all three gates.
__global__ __launch_bounds__(256) void recurrent(const float* __restrict__ Whh,
                                                 const float* __restrict__ bhh,
                                                 const float* __restrict__ Wout,
                                                 const float* __restrict__ bout,
                                                 float* __restrict__ out) {
    __shared__ float sh_h[BB][KC + 2];     // 128 x 66 floats
    __shared__ float sh_w[24][KC + 2];     // 24 gate rows x 66
    __shared__ float sh_row[HH];           // phase-2 hidden row
    __shared__ float sh_log[NL];

    const int tid = threadIdx.x;
    const int cta = blockIdx.x;
    const int g   = tid >> 5;      // 0..7: h-column group
    const int mi  = tid & 31;      // base batch row
    const int base = cta * 8;
    const int col  = base + g;     // this thread's h column

    // -------- per-launch init (graph replays must be deterministic) --------
#pragma unroll
    for (int i = 0; i < 4; i++) g_hbuf[0][cta * 1024 + tid + i * 256] = 0.0f;
    if (cta == 0 && tid < BB) g_prev[tid] = 0;    // start label 'O'
    unsigned sense = g_bar_sense;                 // stable at launch start
    gridbar(sense);

    const float bhr = bhh[col];
    const float bhz = bhh[HH + col];
    const float bhn = bhh[2 * HH + col];

    int cur = 0;
    for (int t = 0; t < TT; t++) {
        // ---- phase 1: gh tile + GRU update for this CTA's 8 h-columns ----
        float gx_r[4], gx_z[4], gx_n[4], hold[4];
#pragma unroll
        for (int i = 0; i < 4; i++) {
            int b = mi + 32 * i;
            size_t row = ((size_t)b * TT + t) * G3;
            int pv = g_prev[b];
            const float* tb = g_tbl + pv * G3;
            gx_r[i] = g_gxw[row + col]            + tb[col];
            gx_z[i] = g_gxw[row + HH + col]       + tb[HH + col];
            gx_n[i] = g_gxw[row + 2 * HH + col]   + tb[2 * HH + col];
            hold[i] = g_hbuf[cur][b * HH + col];
        }

        float accr[4] = {0, 0, 0, 0}, accz[4] = {0, 0, 0, 0}, accn[4] = {0, 0, 0, 0};
        for (int kb = 0; kb < HH; kb += KC) {
            // stage h tile: 128 rows x 64 k (2048 float4)
#pragma unroll
            for (int j = 0; j < 8; j++) {
                int f = tid + j * 256;
                int r = f >> 4, kq = f & 15;
                float4 v = *(const float4*)&g_hbuf[cur][r * HH + kb + kq * 4];
                *(float2*)&sh_h[r][kq * 4]     = make_float2(v.x, v.y);
                *(float2*)&sh_h[r][kq * 4 + 2] = make_float2(v.z, v.w);
            }
            // stage W_hh tile: 24 gate rows x 64 k (384 float4)
#pragma unroll
            for (int j = 0; j < 2; j++) {
                int f = tid + j * 256;
                if (f < 384) {
                    int r = f >> 4, kq = f & 15;
                    int wrow = (r >> 3) * HH + base + (r & 7);
                    float4 v = *(const float4*)&Whh[(size_t)wrow * HH + kb + kq * 4];
                    *(float2*)&sh_w[r][kq * 4]     = make_float2(v.x, v.y);
                    *(float2*)&sh_w[r][kq * 4 + 2] = make_float2(v.z, v.w);
                }
            }
            __syncthreads();
#pragma unroll
            for (int k = 0; k < KC; k += 2) {
                float2 br = *(float2*)&sh_w[g][k];
                float2 bz = *(float2*)&sh_w[8 + g][k];
                float2 bn = *(float2*)&sh_w[16 + g][k];
#pragma unroll
                for (int i = 0; i < 4; i++) {
                    float2 a = *(float2*)&sh_h[mi + 32 * i][k];
                    accr[i] += a.x * br.x + a.y * br.y;
                    accz[i] += a.x * bz.x + a.y * bz.y;
                    accn[i] += a.x * bn.x + a.y * bn.y;
                }
            }
            __syncthreads();
        }
#pragma unroll
        for (int i = 0; i < 4; i++) {
            int b = mi + 32 * i;
            float r = sigmoidf_(gx_r[i] + accr[i] + bhr);
            float z = sigmoidf_(gx_z[i] + accz[i] + bhz);
            float n = tanhf(gx_n[i] + r * (accn[i] + bhn));
            float hn = (1.0f - z) * n + z * hold[i];
            g_hbuf[cur ^ 1][b * HH + col] = hn;
        }
        gridbar(sense);

        // ---- phase 2: logits + masked argmax (CTA b handles batch row b) ----
        {
            const int b = cta;
#pragma unroll
            for (int j = 0; j < 4; j++) {
                int k = tid + j * 256;
                sh_row[k] = g_hbuf[cur ^ 1][b * HH + k];
            }
            __syncthreads();
            int w = tid >> 5, lane = tid & 31;
            for (int l = w; l < NL; l += 8) {
                float s = 0.0f;
                const float* wo = Wout + (size_t)l * HH;
                for (int k = lane; k < HH; k += 32) s += sh_row[k] * wo[k];
#pragma unroll
                for (int off = 16; off > 0; off >>= 1)
                    s += __shfl_down_sync(0xffffffffu, s, off);
                if (lane == 0) sh_log[l] = s;
            }
            __syncthreads();
            if (tid == 0) {
                int pv = g_prev[b];
                float best = -INFINITY;
                int bi = 0;
                float* orow = out + ((size_t)b * TT + t) * NL;
#pragma unroll
                for (int l = 0; l < NL; l++) {
                    float v = sh_log[l] + bout[l] + maskval(pv, l);
                    orow[l] = v;
                    if (v > best) { best = v; bi = l; }
                }
                g_prev[b] = bi;
            }
        }
        gridbar(sense);
        cur ^= 1;
    }
}

// ---------------- launch ----------------
extern "C" void kernel_launch(void* const* d_in, const int* in_sizes, int n_in,
                              void* d_out, int out_size) {
    const float* we   = (const float*)d_in[0];  // [128,512,1024]
    const float* lemb = (const float*)d_in[1];  // [17,128]
    const float* wih  = (const float*)d_in[2];  // [3072,1152]
    const float* whh  = (const float*)d_in[3];  // [3072,1024]
    const float* bih  = (const float*)d_in[4];  // [3072]
    const float* bhh  = (const float*)d_in[5];  // [3072]
    const float* wout = (const float*)d_in[6];  // [17,1024]
    const float* bout = (const float*)d_in[7];  // [17]
    float* out = (float*)d_out;                 // [128,512,17]

    build_table<<<dim3(G3 / 256, NL), 256>>>(lemb, wih, bih);
    gxw_gemm<<<dim3(G3 / BN, (BB * TT) / BM), 256>>>(we, wih);
    recurrent<<<NCTA, 256>>>(whh, bhh, wout, bout, out);
}